// round 2
// baseline (speedup 1.0000x reference)
#include <cuda_runtime.h>
#include <cuda_bf16.h>

#define N_NODES 100000
#define IN_F    128
#define HID     16
#define OUT_F   64

// ---- scratch: __device__ globals (sanctioned; never take their address on host) ----
__device__ float  g_norm_src[N_NODES];
__device__ float  g_norm_dst[N_NODES];
__device__ float  g_deg_out[N_NODES];
__device__ float  g_deg_in[N_NODES];
// buf0: y1 (layer-1 messages), later reused as agg2 (layer-2 accumulator)
// buf1: agg1 (layer-1 accumulator), transformed in place into y2 (layer-2 messages)
__device__ float4 g_buf0[N_NODES * 4];
__device__ float4 g_buf1[N_NODES * 4];

// ---- zero agg1 (buf1) + degree arrays ----
__global__ void k_zero() {
    int i = blockIdx.x * blockDim.x + threadIdx.x;
    if (i < N_NODES * 4) g_buf1[i] = make_float4(0.f, 0.f, 0.f, 0.f);
    if (i < N_NODES)     { g_deg_out[i] = 0.f; g_deg_in[i] = 0.f; }
}

// ---- degree counts ----
__global__ void k_degree(const int* __restrict__ src, const int* __restrict__ dst, int e) {
    int i = blockIdx.x * blockDim.x + threadIdx.x;
    if (i < e) {
        atomicAdd(&g_deg_out[src[i]], 1.f);
        atomicAdd(&g_deg_in [dst[i]], 1.f);
    }
}

// ---- norms: clamp(deg,1)^-1/2 ----
__global__ void k_norms(int n) {
    int i = blockIdx.x * blockDim.x + threadIdx.x;
    if (i < n) {
        g_norm_src[i] = rsqrtf(fmaxf(g_deg_out[i], 1.f));
        g_norm_dst[i] = rsqrtf(fmaxf(g_deg_in [i], 1.f));
    }
}

// ---- layer1 transform: buf0[n][j] = norm_src[n] * sum_k x[n][k] * W1[k][j] ----
// 256 threads/block, 16 nodes/block, 16 threads per node (one per HID output).
__global__ void k_xform(const float* __restrict__ x, const float* __restrict__ W1, int n) {
    __shared__ float sW[IN_F * HID];       // 8 KB
    __shared__ float sX[16 * 129];         // padded rows vs bank conflicts
    int t = threadIdx.x;
    for (int i = t; i < IN_F * HID; i += 256) sW[i] = W1[i];
    int base = blockIdx.x * 16;
    for (int i = t; i < 16 * IN_F; i += 256) {
        int gidx = base * IN_F + i;        // contiguous: coalesced
        sX[(i >> 7) * 129 + (i & 127)] = (gidx < n * IN_F) ? x[gidx] : 0.f;
    }
    __syncthreads();
    int li = t >> 4, j = t & 15;
    int node = base + li;
    if (node >= n) return;
    float acc = 0.f;
    const float* xr = &sX[li * 129];
    #pragma unroll 16
    for (int k = 0; k < IN_F; k++)
        acc = fmaf(xr[k], sW[k * HID + j], acc);
    reinterpret_cast<float*>(g_buf0)[node * HID + j] = acc * g_norm_src[node];
}

// ---- edge scatter: agg[dst] += y[src], 16 floats/edge. One thread per edge. ----
// phase 0: y = buf0 (y1), agg = buf1 (agg1)
// phase 1: y = buf1 (y2), agg = buf0 (agg2)
__global__ void k_scatter(const int* __restrict__ src, const int* __restrict__ dst,
                          int e, int phase) {
    int i = blockIdx.x * blockDim.x + threadIdx.x;
    if (i >= e) return;
    const float4* __restrict__ y   = phase ? g_buf1 : g_buf0;
    float4*       __restrict__ agg = phase ? g_buf0 : g_buf1;
    int s = src[i];
    int d = dst[i];
    // four independent 16B gathers (MLP 4), then four vector reductions
    float4 v0 = y[s * 4 + 0];
    float4 v1 = y[s * 4 + 1];
    float4 v2 = y[s * 4 + 2];
    float4 v3 = y[s * 4 + 3];
    atomicAdd(&agg[d * 4 + 0], v0);
    atomicAdd(&agg[d * 4 + 1], v1);
    atomicAdd(&agg[d * 4 + 2], v2);
    atomicAdd(&agg[d * 4 + 3], v3);
}

// ---- layer1 epilogue fused with layer2 message prep + agg2 zeroing ----
// buf1[i] <- relu(buf1[i]*norm_dst + b1) * norm_src   (in place, elementwise)
// buf0[i] <- 0                                        (agg2 init for scatter 2)
__global__ void k_post(const float* __restrict__ b1, int n) {
    int i = blockIdx.x * blockDim.x + threadIdx.x;
    if (i >= n * HID) return;
    int node = i >> 4, j = i & 15;
    float* b1f = reinterpret_cast<float*>(g_buf1);
    float v = b1f[i];
    v = fmaf(v, g_norm_dst[node], b1[j]);
    v = fmaxf(v, 0.f) * g_norm_src[node];
    b1f[i] = v;
    reinterpret_cast<float*>(g_buf0)[i] = 0.f;
}

// ---- final: out[n][j] = norm_dst[n] * sum_k buf0[n][k]*W2[k][j] + b2[j] ----
__global__ void k_final(const float* __restrict__ W2, const float* __restrict__ b2,
                        float* __restrict__ out, int n) {
    int i = blockIdx.x * blockDim.x + threadIdx.x;
    if (i >= n * OUT_F) return;
    int node = i >> 6, j = i & 63;
    const float* a = reinterpret_cast<const float*>(g_buf0) + node * HID;
    float acc = 0.f;
    #pragma unroll
    for (int k = 0; k < HID; k++)
        acc = fmaf(a[k], W2[k * OUT_F + j], acc);
    out[i] = fmaf(acc, g_norm_dst[node], b2[j]);
}

extern "C" void kernel_launch(void* const* d_in, const int* in_sizes, int n_in,
                              void* d_out, int out_size) {
    const float* x   = (const float*)d_in[0];
    const int*   src = (const int*)  d_in[1];
    const int*   dst = (const int*)  d_in[2];
    const float* W1  = (const float*)d_in[3];
    const float* b1  = (const float*)d_in[4];
    const float* W2  = (const float*)d_in[5];
    const float* b2  = (const float*)d_in[6];
    float* out = (float*)d_out;

    int n = in_sizes[0] / IN_F;    // 100000
    int e = in_sizes[1];           // 3200000

    const int T = 256;
    k_zero  <<<(N_NODES * 4 + T - 1) / T, T>>>();
    k_degree<<<(e + T - 1) / T, T>>>(src, dst, e);
    k_norms <<<(n + T - 1) / T, T>>>(n);
    k_xform <<<(n + 15) / 16, T>>>(x, W1, n);
    k_scatter<<<(e + T - 1) / T, T>>>(src, dst, e, 0);
    k_post  <<<(n * HID + T - 1) / T, T>>>(b1, n);
    k_scatter<<<(e + T - 1) / T, T>>>(src, dst, e, 1);
    k_final <<<(n * OUT_F + T - 1) / T, T>>>(W2, b2, out, n);
}

// round 3
// speedup vs baseline: 1.1096x; 1.1096x over previous
#include <cuda_runtime.h>
#include <cuda_bf16.h>

#define N_NODES 100000
#define IN_F    128
#define HID     16
#define OUT_F   64
#define XN      64      // nodes per block in k_xform

// ---- scratch: __device__ globals (never take their address on host) ----
__device__ float  g_norm_src[N_NODES];
__device__ float  g_norm_dst[N_NODES];
__device__ float  g_deg_out[N_NODES];
__device__ float  g_deg_in[N_NODES];
// buf0: y1 (layer-1 messages), later reused as agg2 (layer-2 accumulator)
// buf1: agg1 (layer-1 accumulator), transformed in place into y2 (layer-2 messages)
__device__ float4 g_buf0[N_NODES * 4];
__device__ float4 g_buf1[N_NODES * 4];

// ---- zero agg1 (buf1) + degree arrays ----
__global__ void k_zero() {
    int i = blockIdx.x * blockDim.x + threadIdx.x;
    if (i < N_NODES * 4) g_buf1[i] = make_float4(0.f, 0.f, 0.f, 0.f);
    if (i < N_NODES)     { g_deg_out[i] = 0.f; g_deg_in[i] = 0.f; }
}

// ---- degree counts ----
__global__ void k_degree(const int* __restrict__ src, const int* __restrict__ dst, int e) {
    int i = blockIdx.x * blockDim.x + threadIdx.x;
    if (i < e) {
        atomicAdd(&g_deg_out[src[i]], 1.f);
        atomicAdd(&g_deg_in [dst[i]], 1.f);
    }
}

// ---- norms: clamp(deg,1)^-1/2 ----
__global__ void k_norms(int n) {
    int i = blockIdx.x * blockDim.x + threadIdx.x;
    if (i < n) {
        g_norm_src[i] = rsqrtf(fmaxf(g_deg_out[i], 1.f));
        g_norm_dst[i] = rsqrtf(fmaxf(g_deg_in [i], 1.f));
    }
}

// ---- layer1 transform: buf0[n][j] = norm_src[n] * sum_k x[n][k] * W1[k][j] ----
// One thread per node, 16 accumulators in registers.
// Per k: 1 conflict-free scalar LDS (x) + 4 broadcast LDS.128 (W) + 16 FMA.
__global__ void __launch_bounds__(XN) k_xform(const float* __restrict__ x,
                                              const float* __restrict__ W1, int n) {
    __shared__ float sW[IN_F * HID];       // 8 KB
    __shared__ float sX[XN * 129];         // 33 KB, row stride 129 (odd word) -> no conflicts
    int t = threadIdx.x;                   // 0..63
    // W: 2048 floats = 512 float4, coalesced
    for (int i = t; i < IN_F * HID / 4; i += XN)
        reinterpret_cast<float4*>(sW)[i] = reinterpret_cast<const float4*>(W1)[i];
    int base = blockIdx.x * XN;
    // x tile: XN rows of 128 floats, loaded coalesced as float4, stored to padded rows
    for (int i = t; i < XN * IN_F / 4; i += XN) {
        int node = i >> 5;                 // 32 float4 per row
        int c4   = i & 31;
        float4 v = make_float4(0.f, 0.f, 0.f, 0.f);
        if (base + node < n)
            v = *reinterpret_cast<const float4*>(x + (size_t)(base + node) * IN_F + c4 * 4);
        float* dp = &sX[node * 129 + c4 * 4];
        dp[0] = v.x; dp[1] = v.y; dp[2] = v.z; dp[3] = v.w;
    }
    __syncthreads();
    int node = base + t;
    if (node >= n) return;
    float acc[HID];
    #pragma unroll
    for (int j = 0; j < HID; j++) acc[j] = 0.f;
    const float* xr = &sX[t * 129];
    #pragma unroll 4
    for (int k = 0; k < IN_F; k++) {
        float xk = xr[k];                                  // bank = (t+k)%32: conflict-free
        const float4* wr = reinterpret_cast<const float4*>(&sW[k * HID]);
        float4 w0 = wr[0], w1 = wr[1], w2 = wr[2], w3 = wr[3];  // broadcast
        acc[0]  = fmaf(xk, w0.x, acc[0]);  acc[1]  = fmaf(xk, w0.y, acc[1]);
        acc[2]  = fmaf(xk, w0.z, acc[2]);  acc[3]  = fmaf(xk, w0.w, acc[3]);
        acc[4]  = fmaf(xk, w1.x, acc[4]);  acc[5]  = fmaf(xk, w1.y, acc[5]);
        acc[6]  = fmaf(xk, w1.z, acc[6]);  acc[7]  = fmaf(xk, w1.w, acc[7]);
        acc[8]  = fmaf(xk, w2.x, acc[8]);  acc[9]  = fmaf(xk, w2.y, acc[9]);
        acc[10] = fmaf(xk, w2.z, acc[10]); acc[11] = fmaf(xk, w2.w, acc[11]);
        acc[12] = fmaf(xk, w3.x, acc[12]); acc[13] = fmaf(xk, w3.y, acc[13]);
        acc[14] = fmaf(xk, w3.z, acc[14]); acc[15] = fmaf(xk, w3.w, acc[15]);
    }
    float ns = g_norm_src[node];
    float4* op = &g_buf0[node * 4];
    #pragma unroll
    for (int q = 0; q < 4; q++)
        op[q] = make_float4(acc[q*4+0]*ns, acc[q*4+1]*ns, acc[q*4+2]*ns, acc[q*4+3]*ns);
}

// ---- edge scatter: agg[dst] += y[src], 16 floats/edge. One thread per edge. ----
// phase 0: y = buf0 (y1), agg = buf1 (agg1)
// phase 1: y = buf1 (y2), agg = buf0 (agg2)
__global__ void k_scatter(const int* __restrict__ src, const int* __restrict__ dst,
                          int e, int phase) {
    int i = blockIdx.x * blockDim.x + threadIdx.x;
    if (i >= e) return;
    const float4* __restrict__ y   = phase ? g_buf1 : g_buf0;
    float4*       __restrict__ agg = phase ? g_buf0 : g_buf1;
    int s = src[i];
    int d = dst[i];
    float4 v0 = y[s * 4 + 0];
    float4 v1 = y[s * 4 + 1];
    float4 v2 = y[s * 4 + 2];
    float4 v3 = y[s * 4 + 3];
    atomicAdd(&agg[d * 4 + 0], v0);
    atomicAdd(&agg[d * 4 + 1], v1);
    atomicAdd(&agg[d * 4 + 2], v2);
    atomicAdd(&agg[d * 4 + 3], v3);
}

// ---- layer1 epilogue fused with layer2 message prep + agg2 zeroing ----
__global__ void k_post(const float* __restrict__ b1, int n) {
    int i = blockIdx.x * blockDim.x + threadIdx.x;
    if (i >= n * HID) return;
    int node = i >> 4, j = i & 15;
    float* b1f = reinterpret_cast<float*>(g_buf1);
    float v = b1f[i];
    v = fmaf(v, g_norm_dst[node], b1[j]);
    v = fmaxf(v, 0.f) * g_norm_src[node];
    b1f[i] = v;
    reinterpret_cast<float*>(g_buf0)[i] = 0.f;
}

// ---- final: out[n][j] = norm_dst[n] * sum_k buf0[n][k]*W2[k][j] + b2[j] ----
__global__ void k_final(const float* __restrict__ W2, const float* __restrict__ b2,
                        float* __restrict__ out, int n) {
    int i = blockIdx.x * blockDim.x + threadIdx.x;
    if (i >= n * OUT_F) return;
    int node = i >> 6, j = i & 63;
    const float* a = reinterpret_cast<const float*>(g_buf0) + node * HID;
    float acc = 0.f;
    #pragma unroll
    for (int k = 0; k < HID; k++)
        acc = fmaf(a[k], W2[k * OUT_F + j], acc);
    out[i] = fmaf(acc, g_norm_dst[node], b2[j]);
}

extern "C" void kernel_launch(void* const* d_in, const int* in_sizes, int n_in,
                              void* d_out, int out_size) {
    const float* x   = (const float*)d_in[0];
    const int*   src = (const int*)  d_in[1];
    const int*   dst = (const int*)  d_in[2];
    const float* W1  = (const float*)d_in[3];
    const float* b1  = (const float*)d_in[4];
    const float* W2  = (const float*)d_in[5];
    const float* b2  = (const float*)d_in[6];
    float* out = (float*)d_out;

    int n = in_sizes[0] / IN_F;    // 100000
    int e = in_sizes[1];           // 3200000

    const int T = 256;
    k_zero  <<<(N_NODES * 4 + T - 1) / T, T>>>();
    k_degree<<<(e + T - 1) / T, T>>>(src, dst, e);
    k_norms <<<(n + T - 1) / T, T>>>(n);
    k_xform <<<(n + XN - 1) / XN, XN>>>(x, W1, n);
    k_scatter<<<(e + T - 1) / T, T>>>(src, dst, e, 0);
    k_post  <<<(n * HID + T - 1) / T, T>>>(b1, n);
    k_scatter<<<(e + T - 1) / T, T>>>(src, dst, e, 1);
    k_final <<<(n * OUT_F + T - 1) / T, T>>>(W2, b2, out, n);
}

// round 4
// speedup vs baseline: 1.5834x; 1.4270x over previous
#include <cuda_runtime.h>
#include <cuda_bf16.h>

#define N_NODES 100000
#define N_EDGES 3200000
#define IN_F    128
#define HID     16
#define OUT_F   64
#define XB      256     // threads/block in k_xform (1 node per thread, k-chunked)
#define SCB     1024    // scan block size

// ---- scratch: __device__ globals (never referenced from host code) ----
__device__ float g_norm_src[N_NODES];
__device__ float g_norm_dst[N_NODES];
__device__ int   g_deg_out[N_NODES];
__device__ int   g_deg_in[N_NODES];
__device__ int   g_row_start[N_NODES + 1];
__device__ int   g_cursor[N_NODES];
__device__ int   g_blocksum[(N_NODES + SCB - 1) / SCB + 1];
__device__ int   g_csr_src[N_EDGES];
// buf0: y1 (layer-1 messages), later reused as agg2 (layer-2 accumulator)
// buf1: y2 (layer-2 messages, written by gather-0 with fused relu/bias/norm)
__device__ float4 g_buf0[N_NODES * 4];
__device__ float4 g_buf1[N_NODES * 4];

// ---- zero degree counters ----
__global__ void k_zero() {
    int i = blockIdx.x * blockDim.x + threadIdx.x;
    if (i < N_NODES) { g_deg_out[i] = 0; g_deg_in[i] = 0; }
}

// ---- int degree histograms ----
__global__ void k_hist(const int* __restrict__ src, const int* __restrict__ dst, int e) {
    int i = blockIdx.x * blockDim.x + threadIdx.x;
    if (i < e) {
        atomicAdd(&g_deg_out[src[i]], 1);
        atomicAdd(&g_deg_in [dst[i]], 1);
    }
}

// ---- norms: clamp(deg,1)^-1/2 ----
__global__ void k_norms(int n) {
    int i = blockIdx.x * blockDim.x + threadIdx.x;
    if (i < n) {
        g_norm_src[i] = rsqrtf((float)max(g_deg_out[i], 1));
        g_norm_dst[i] = rsqrtf((float)max(g_deg_in [i], 1));
    }
}

// ---- scan pass A: per-block sums of in-degree ----
__global__ void k_scan1(int n) {
    __shared__ int sp[SCB];
    int t = threadIdx.x;
    int i = blockIdx.x * SCB + t;
    int v = (i < n) ? g_deg_in[i] : 0;
    sp[t] = v; __syncthreads();
    for (int d = SCB / 2; d > 0; d >>= 1) {
        if (t < d) sp[t] += sp[t + d];
        __syncthreads();
    }
    if (t == 0) g_blocksum[blockIdx.x] = sp[0];
}

// ---- scan pass B: exclusive scan of block sums (single block) ----
__global__ void k_scan2(int nb, int e) {
    __shared__ int sp[SCB];
    int t = threadIdx.x;
    int v = (t < nb) ? g_blocksum[t] : 0;
    sp[t] = v; __syncthreads();
    for (int d = 1; d < SCB; d <<= 1) {
        int w = (t >= d) ? sp[t - d] : 0;
        __syncthreads();
        sp[t] += w;
        __syncthreads();
    }
    if (t < nb) g_blocksum[t] = sp[t] - v;   // exclusive
    if (t == 0) g_row_start[N_NODES] = e;
}

// ---- scan pass C: in-block exclusive scan + block offset -> row_start, cursor ----
__global__ void k_scan3(int n) {
    __shared__ int sp[SCB];
    int t = threadIdx.x;
    int i = blockIdx.x * SCB + t;
    int v = (i < n) ? g_deg_in[i] : 0;
    sp[t] = v; __syncthreads();
    for (int d = 1; d < SCB; d <<= 1) {
        int w = (t >= d) ? sp[t - d] : 0;
        __syncthreads();
        sp[t] += w;
        __syncthreads();
    }
    if (i < n) {
        int off = g_blocksum[blockIdx.x] + sp[t] - v;
        g_row_start[i] = off;
        g_cursor[i]    = off;
    }
}

// ---- CSR placement: csr_src[cursor[dst]++] = src ----
__global__ void k_place(const int* __restrict__ src, const int* __restrict__ dst, int e) {
    int i = blockIdx.x * blockDim.x + threadIdx.x;
    if (i < e) {
        int pos = atomicAdd(&g_cursor[dst[i]], 1);
        g_csr_src[pos] = src[i];
    }
}

// ---- layer1 transform: buf0[v][j] = norm_src[v] * sum_k x[v][k]*W1[k][j] ----
// 256 threads, 1 node/thread, 16 reg accumulators, k chunked by 32 (smem ~42 KB).
__global__ void __launch_bounds__(XB) k_xform(const float* __restrict__ x,
                                              const float* __restrict__ W1, int n) {
    __shared__ float sW[IN_F * HID];        // 8 KB
    __shared__ float sX[XB * 33];           // 33.8 KB, row stride 33 -> conflict-free
    int t = threadIdx.x;
    for (int i = t; i < IN_F * HID / 4; i += XB)
        reinterpret_cast<float4*>(sW)[i] = reinterpret_cast<const float4*>(W1)[i];
    int base = blockIdx.x * XB;
    float acc[HID];
    #pragma unroll
    for (int j = 0; j < HID; j++) acc[j] = 0.f;

    for (int kc = 0; kc < IN_F; kc += 32) {
        __syncthreads();
        // stage chunk: XB rows x 32 cols, coalesced float4 loads
        for (int i = t; i < XB * 8; i += XB) {
            int node = i >> 3, c4 = i & 7;
            float4 v = make_float4(0.f, 0.f, 0.f, 0.f);
            if (base + node < n)
                v = *reinterpret_cast<const float4*>(
                        x + (size_t)(base + node) * IN_F + kc + c4 * 4);
            float* dp = &sX[node * 33 + c4 * 4];
            dp[0] = v.x; dp[1] = v.y; dp[2] = v.z; dp[3] = v.w;
        }
        __syncthreads();
        const float* xr = &sX[t * 33];
        #pragma unroll
        for (int kk = 0; kk < 32; kk++) {
            float xk = xr[kk];                          // bank (t+kk)%32: conflict-free
            const float4* wr = reinterpret_cast<const float4*>(&sW[(kc + kk) * HID]);
            float4 w0 = wr[0], w1 = wr[1], w2 = wr[2], w3 = wr[3];  // broadcast
            acc[0]  = fmaf(xk, w0.x, acc[0]);  acc[1]  = fmaf(xk, w0.y, acc[1]);
            acc[2]  = fmaf(xk, w0.z, acc[2]);  acc[3]  = fmaf(xk, w0.w, acc[3]);
            acc[4]  = fmaf(xk, w1.x, acc[4]);  acc[5]  = fmaf(xk, w1.y, acc[5]);
            acc[6]  = fmaf(xk, w1.z, acc[6]);  acc[7]  = fmaf(xk, w1.w, acc[7]);
            acc[8]  = fmaf(xk, w2.x, acc[8]);  acc[9]  = fmaf(xk, w2.y, acc[9]);
            acc[10] = fmaf(xk, w2.z, acc[10]); acc[11] = fmaf(xk, w2.w, acc[11]);
            acc[12] = fmaf(xk, w3.x, acc[12]); acc[13] = fmaf(xk, w3.y, acc[13]);
            acc[14] = fmaf(xk, w3.z, acc[14]); acc[15] = fmaf(xk, w3.w, acc[15]);
        }
    }
    int node = base + t;
    if (node >= n) return;
    float ns = g_norm_src[node];
    float4* op = &g_buf0[node * 4];
    #pragma unroll
    for (int q = 0; q < 4; q++)
        op[q] = make_float4(acc[q*4]*ns, acc[q*4+1]*ns, acc[q*4+2]*ns, acc[q*4+3]*ns);
}

// ---- CSR gather: 4 lanes per node, lane p owns float4 part p. No atomics. ----
// phase 0: in buf0 (y1) -> out buf1 = relu(sum*norm_dst + b1)*norm_src   (y2)
// phase 1: in buf1 (y2) -> out buf0 = sum                                 (agg2)
__global__ void k_gather(int n, int phase, const float* __restrict__ b1) {
    int gt = blockIdx.x * blockDim.x + threadIdx.x;
    int node = gt >> 2;
    int p    = gt & 3;
    if (node >= n) return;
    const float4* __restrict__ y = phase ? g_buf1 : g_buf0;
    int beg = g_row_start[node], end = g_row_start[node + 1];
    float4 acc = make_float4(0.f, 0.f, 0.f, 0.f);
    int i = beg;
    for (; i + 4 <= end; i += 4) {
        int s  = g_csr_src[i + p];            // lane p fetches edge i+p
        int s0 = __shfl_sync(0xffffffffu, s, 0, 4);
        int s1 = __shfl_sync(0xffffffffu, s, 1, 4);
        int s2 = __shfl_sync(0xffffffffu, s, 2, 4);
        int s3 = __shfl_sync(0xffffffffu, s, 3, 4);
        float4 v0 = y[s0 * 4 + p];
        float4 v1 = y[s1 * 4 + p];
        float4 v2 = y[s2 * 4 + p];
        float4 v3 = y[s3 * 4 + p];
        acc.x += v0.x + v1.x + v2.x + v3.x;
        acc.y += v0.y + v1.y + v2.y + v3.y;
        acc.z += v0.z + v1.z + v2.z + v3.z;
        acc.w += v0.w + v1.w + v2.w + v3.w;
    }
    for (; i < end; i++) {
        int s = g_csr_src[i];
        float4 v = y[s * 4 + p];
        acc.x += v.x; acc.y += v.y; acc.z += v.z; acc.w += v.w;
    }
    if (phase == 0) {
        float nd = g_norm_dst[node], ns = g_norm_src[node];
        float4 bv = reinterpret_cast<const float4*>(b1)[p];
        acc.x = fmaxf(fmaf(acc.x, nd, bv.x), 0.f) * ns;
        acc.y = fmaxf(fmaf(acc.y, nd, bv.y), 0.f) * ns;
        acc.z = fmaxf(fmaf(acc.z, nd, bv.z), 0.f) * ns;
        acc.w = fmaxf(fmaf(acc.w, nd, bv.w), 0.f) * ns;
        g_buf1[node * 4 + p] = acc;
    } else {
        g_buf0[node * 4 + p] = acc;
    }
}

// ---- final: out[v][j] = norm_dst[v] * sum_k buf0[v][k]*W2[k][j] + b2[j] ----
__global__ void k_final(const float* __restrict__ W2, const float* __restrict__ b2,
                        float* __restrict__ out, int n) {
    int i = blockIdx.x * blockDim.x + threadIdx.x;
    if (i >= n * OUT_F) return;
    int node = i >> 6, j = i & 63;
    const float* a = reinterpret_cast<const float*>(g_buf0) + node * HID;
    float acc = 0.f;
    #pragma unroll
    for (int k = 0; k < HID; k++)
        acc = fmaf(a[k], W2[k * OUT_F + j], acc);
    out[i] = fmaf(acc, g_norm_dst[node], b2[j]);
}

extern "C" void kernel_launch(void* const* d_in, const int* in_sizes, int n_in,
                              void* d_out, int out_size) {
    const float* x   = (const float*)d_in[0];
    const int*   src = (const int*)  d_in[1];
    const int*   dst = (const int*)  d_in[2];
    const float* W1  = (const float*)d_in[3];
    const float* b1  = (const float*)d_in[4];
    const float* W2  = (const float*)d_in[5];
    const float* b2  = (const float*)d_in[6];
    float* out = (float*)d_out;

    int n = in_sizes[0] / IN_F;    // 100000
    int e = in_sizes[1];           // 3200000
    int nb = (n + SCB - 1) / SCB;  // scan blocks

    const int T = 256;
    k_zero  <<<(N_NODES + T - 1) / T, T>>>();
    k_hist  <<<(e + T - 1) / T, T>>>(src, dst, e);
    k_norms <<<(n + T - 1) / T, T>>>(n);
    k_scan1 <<<nb, SCB>>>(n);
    k_scan2 <<<1, SCB>>>(nb, e);
    k_scan3 <<<nb, SCB>>>(n);
    k_place <<<(e + T - 1) / T, T>>>(src, dst, e);
    k_xform <<<(n + XB - 1) / XB, XB>>>(x, W1, n);
    k_gather<<<(n * 4 + T - 1) / T, T>>>(n, 0, b1);
    k_gather<<<(n * 4 + T - 1) / T, T>>>(n, 1, b1);
    k_final <<<(n * OUT_F + T - 1) / T, T>>>(W2, b2, out, n);
}

// round 5
// speedup vs baseline: 1.6474x; 1.0404x over previous
#include <cuda_runtime.h>
#include <cuda_bf16.h>

#define N_NODES 100000
#define N_EDGES 3200000
#define IN_F    128
#define HID     16
#define OUT_F   64
#define XB      256     // threads/block in k_xform
#define SCB     1024    // scan block size
#define FULL    0xffffffffu

// ---- scratch: __device__ globals ----
__device__ float g_norm_src[N_NODES];
__device__ float g_norm_dst[N_NODES];
__device__ int   g_deg_out[N_NODES];
__device__ int   g_deg_in[N_NODES];
__device__ int   g_row_start[N_NODES + 1];
__device__ int   g_cursor[N_NODES];
__device__ int   g_blocksum[(N_NODES + SCB - 1) / SCB + 1];
__device__ int   g_csr_src[N_EDGES];
__device__ float4 g_y1[N_NODES * 4];   // layer-1 messages
__device__ float4 g_y2[N_NODES * 4];   // layer-2 messages

// ---- int degree histograms (4 edges per thread via int4) ----
__global__ void k_hist(const int* __restrict__ src, const int* __restrict__ dst, int e4) {
    int i = blockIdx.x * blockDim.x + threadIdx.x;
    if (i >= e4) return;
    int4 s = reinterpret_cast<const int4*>(src)[i];
    int4 d = reinterpret_cast<const int4*>(dst)[i];
    atomicAdd(&g_deg_out[s.x], 1); atomicAdd(&g_deg_out[s.y], 1);
    atomicAdd(&g_deg_out[s.z], 1); atomicAdd(&g_deg_out[s.w], 1);
    atomicAdd(&g_deg_in [d.x], 1); atomicAdd(&g_deg_in [d.y], 1);
    atomicAdd(&g_deg_in [d.z], 1); atomicAdd(&g_deg_in [d.w], 1);
}

// ---- norms ----
__global__ void k_norms(int n) {
    int i = blockIdx.x * blockDim.x + threadIdx.x;
    if (i < n) {
        g_norm_src[i] = rsqrtf((float)max(g_deg_out[i], 1));
        g_norm_dst[i] = rsqrtf((float)max(g_deg_in [i], 1));
    }
}

// ---- scan pass A: per-block sums of in-degree ----
__global__ void k_scan1(int n) {
    __shared__ int sp[SCB];
    int t = threadIdx.x;
    int i = blockIdx.x * SCB + t;
    sp[t] = (i < n) ? g_deg_in[i] : 0;
    __syncthreads();
    for (int d = SCB / 2; d > 0; d >>= 1) {
        if (t < d) sp[t] += sp[t + d];
        __syncthreads();
    }
    if (t == 0) g_blocksum[blockIdx.x] = sp[0];
}

// ---- scan pass B: exclusive scan of block sums (single block) ----
__global__ void k_scan2(int nb, int e) {
    __shared__ int sp[SCB];
    int t = threadIdx.x;
    int v = (t < nb) ? g_blocksum[t] : 0;
    sp[t] = v; __syncthreads();
    for (int d = 1; d < SCB; d <<= 1) {
        int w = (t >= d) ? sp[t - d] : 0;
        __syncthreads();
        sp[t] += w;
        __syncthreads();
    }
    if (t < nb) g_blocksum[t] = sp[t] - v;
    if (t == 0) g_row_start[N_NODES] = e;
}

// ---- scan pass C: in-block exclusive scan + block offset ----
__global__ void k_scan3(int n) {
    __shared__ int sp[SCB];
    int t = threadIdx.x;
    int i = blockIdx.x * SCB + t;
    int v = (i < n) ? g_deg_in[i] : 0;
    sp[t] = v; __syncthreads();
    for (int d = 1; d < SCB; d <<= 1) {
        int w = (t >= d) ? sp[t - d] : 0;
        __syncthreads();
        sp[t] += w;
        __syncthreads();
    }
    if (i < n) {
        int off = g_blocksum[blockIdx.x] + sp[t] - v;
        g_row_start[i] = off;
        g_cursor[i]    = off;
    }
}

// ---- CSR placement ----
__global__ void k_place(const int* __restrict__ src, const int* __restrict__ dst, int e) {
    int i = blockIdx.x * blockDim.x + threadIdx.x;
    if (i < e) {
        int pos = atomicAdd(&g_cursor[dst[i]], 1);
        g_csr_src[pos] = src[i];
    }
}

// ---- layer1 transform: y1[v][j] = norm_src[v] * sum_k x[v][k]*W1[k][j] ----
__global__ void __launch_bounds__(XB) k_xform(const float* __restrict__ x,
                                              const float* __restrict__ W1, int n) {
    __shared__ float sW[IN_F * HID];
    __shared__ float sX[XB * 33];
    int t = threadIdx.x;
    for (int i = t; i < IN_F * HID / 4; i += XB)
        reinterpret_cast<float4*>(sW)[i] = reinterpret_cast<const float4*>(W1)[i];
    int base = blockIdx.x * XB;
    float acc[HID];
    #pragma unroll
    for (int j = 0; j < HID; j++) acc[j] = 0.f;

    for (int kc = 0; kc < IN_F; kc += 32) {
        __syncthreads();
        for (int i = t; i < XB * 8; i += XB) {
            int node = i >> 3, c4 = i & 7;
            float4 v = make_float4(0.f, 0.f, 0.f, 0.f);
            if (base + node < n)
                v = *reinterpret_cast<const float4*>(
                        x + (size_t)(base + node) * IN_F + kc + c4 * 4);
            float* dp = &sX[node * 33 + c4 * 4];
            dp[0] = v.x; dp[1] = v.y; dp[2] = v.z; dp[3] = v.w;
        }
        __syncthreads();
        const float* xr = &sX[t * 33];
        #pragma unroll
        for (int kk = 0; kk < 32; kk++) {
            float xk = xr[kk];
            const float4* wr = reinterpret_cast<const float4*>(&sW[(kc + kk) * HID]);
            float4 w0 = wr[0], w1 = wr[1], w2 = wr[2], w3 = wr[3];
            acc[0]  = fmaf(xk, w0.x, acc[0]);  acc[1]  = fmaf(xk, w0.y, acc[1]);
            acc[2]  = fmaf(xk, w0.z, acc[2]);  acc[3]  = fmaf(xk, w0.w, acc[3]);
            acc[4]  = fmaf(xk, w1.x, acc[4]);  acc[5]  = fmaf(xk, w1.y, acc[5]);
            acc[6]  = fmaf(xk, w1.z, acc[6]);  acc[7]  = fmaf(xk, w1.w, acc[7]);
            acc[8]  = fmaf(xk, w2.x, acc[8]);  acc[9]  = fmaf(xk, w2.y, acc[9]);
            acc[10] = fmaf(xk, w2.z, acc[10]); acc[11] = fmaf(xk, w2.w, acc[11]);
            acc[12] = fmaf(xk, w3.x, acc[12]); acc[13] = fmaf(xk, w3.y, acc[13]);
            acc[14] = fmaf(xk, w3.z, acc[14]); acc[15] = fmaf(xk, w3.w, acc[15]);
        }
    }
    int node = base + t;
    if (node >= n) return;
    float ns = g_norm_src[node];
    float4* op = &g_y1[node * 4];
    #pragma unroll
    for (int q = 0; q < 4; q++)
        op[q] = make_float4(acc[q*4]*ns, acc[q*4+1]*ns, acc[q*4+2]*ns, acc[q*4+3]*ns);
}

// ---- warp-per-node aggregation core: returns float4 part p for this lane group ----
// lane = e_sub*4 + p; 8 edges per iteration, csr read broadcast within groups,
// MLP=8 independent 16B gathers, stride-4 shuffle-tree reduction at the end.
__device__ __forceinline__ float4 warp_aggregate(const float4* __restrict__ y,
                                                 int beg, int end, int e_sub, int p) {
    float4 acc = make_float4(0.f, 0.f, 0.f, 0.f);
    for (int i = beg; i < end; i += 8) {
        int idx = i + e_sub;
        if (idx < end) {
            int s = g_csr_src[idx];        // same addr across the 4 lanes of a group
            float4 v = y[s * 4 + p];
            acc.x += v.x; acc.y += v.y; acc.z += v.z; acc.w += v.w;
        }
    }
    #pragma unroll
    for (int off = 16; off >= 4; off >>= 1) {
        acc.x += __shfl_down_sync(FULL, acc.x, off);
        acc.y += __shfl_down_sync(FULL, acc.y, off);
        acc.z += __shfl_down_sync(FULL, acc.z, off);
        acc.w += __shfl_down_sync(FULL, acc.w, off);
    }
    return acc;   // valid on lanes 0..3 (lane == p)
}

// ---- gather layer 1: y2 = relu(agg(y1)*norm_dst + b1) * norm_src ----
__global__ void __launch_bounds__(256) k_gather1(const float* __restrict__ b1, int n) {
    int warp = (blockIdx.x * blockDim.x + threadIdx.x) >> 5;
    if (warp >= n) return;
    int lane = threadIdx.x & 31;
    int e_sub = lane >> 2, p = lane & 3;
    int beg = g_row_start[warp], end = g_row_start[warp + 1];
    float4 acc = warp_aggregate(g_y1, beg, end, e_sub, p);
    if (lane < 4) {
        float nd = g_norm_dst[warp], ns = g_norm_src[warp];
        float4 bv = reinterpret_cast<const float4*>(b1)[p];
        acc.x = fmaxf(fmaf(acc.x, nd, bv.x), 0.f) * ns;
        acc.y = fmaxf(fmaf(acc.y, nd, bv.y), 0.f) * ns;
        acc.z = fmaxf(fmaf(acc.z, nd, bv.z), 0.f) * ns;
        acc.w = fmaxf(fmaf(acc.w, nd, bv.w), 0.f) * ns;
        g_y2[warp * 4 + p] = acc;
    }
}

// ---- gather layer 2 fused with final: out = agg(y2)@W2 * norm_dst + b2 ----
// 8 warps/block; W2 (4KB) + b2 staged in smem. Each lane emits 2 of 64 outputs.
__global__ void __launch_bounds__(256) k_gather2(const float* __restrict__ W2,
                                                 const float* __restrict__ b2,
                                                 float* __restrict__ out, int n) {
    __shared__ float sW2[HID * OUT_F];    // 4 KB, [k][j]
    __shared__ float sB2[OUT_F];
    int t = threadIdx.x;
    for (int i = t; i < HID * OUT_F / 4; i += 256)
        reinterpret_cast<float4*>(sW2)[i] = reinterpret_cast<const float4*>(W2)[i];
    if (t < OUT_F) sB2[t] = b2[t];
    __syncthreads();

    int warp = (blockIdx.x * blockDim.x + t) >> 5;
    if (warp >= n) return;
    int lane = t & 31;
    int e_sub = lane >> 2, p = lane & 3;
    int beg = g_row_start[warp], end = g_row_start[warp + 1];
    float4 acc = warp_aggregate(g_y2, beg, end, e_sub, p);

    // broadcast the 16 agg values (lanes 0..3 hold parts 0..3) to all lanes
    float a[HID];
    #pragma unroll
    for (int q = 0; q < 4; q++) {
        a[q*4+0] = __shfl_sync(FULL, acc.x, q);
        a[q*4+1] = __shfl_sync(FULL, acc.y, q);
        a[q*4+2] = __shfl_sync(FULL, acc.z, q);
        a[q*4+3] = __shfl_sync(FULL, acc.w, q);
    }
    // each lane computes outputs j = 2*lane, 2*lane+1
    float o0 = 0.f, o1 = 0.f;
    const float2* w2v = reinterpret_cast<const float2*>(sW2);
    #pragma unroll
    for (int k = 0; k < HID; k++) {
        float2 w = w2v[k * (OUT_F / 2) + lane];   // 8B/lane, conflict-free
        o0 = fmaf(a[k], w.x, o0);
        o1 = fmaf(a[k], w.y, o1);
    }
    float nd = g_norm_dst[warp];
    float2 bb = reinterpret_cast<const float2*>(sB2)[lane];
    float2 res = make_float2(fmaf(o0, nd, bb.x), fmaf(o1, nd, bb.y));
    reinterpret_cast<float2*>(out)[warp * (OUT_F / 2) + lane] = res;
}

extern "C" void kernel_launch(void* const* d_in, const int* in_sizes, int n_in,
                              void* d_out, int out_size) {
    const float* x   = (const float*)d_in[0];
    const int*   src = (const int*)  d_in[1];
    const int*   dst = (const int*)  d_in[2];
    const float* W1  = (const float*)d_in[3];
    const float* b1  = (const float*)d_in[4];
    const float* W2  = (const float*)d_in[5];
    const float* b2  = (const float*)d_in[6];
    float* out = (float*)d_out;

    int n = in_sizes[0] / IN_F;    // 100000
    int e = in_sizes[1];           // 3200000
    int nb = (n + SCB - 1) / SCB;

    // zero degree counters via memset (capturable, no allocation)
    void* p_dego = nullptr; void* p_degi = nullptr;
    cudaGetSymbolAddress(&p_dego, g_deg_out);
    cudaGetSymbolAddress(&p_degi, g_deg_in);
    cudaMemsetAsync(p_dego, 0, N_NODES * sizeof(int));
    cudaMemsetAsync(p_degi, 0, N_NODES * sizeof(int));

    const int T = 256;
    int e4 = e / 4;
    k_hist  <<<(e4 + T - 1) / T, T>>>(src, dst, e4);
    k_norms <<<(n + T - 1) / T, T>>>(n);
    k_scan1 <<<nb, SCB>>>(n);
    k_scan2 <<<1, SCB>>>(nb, e);
    k_scan3 <<<nb, SCB>>>(n);
    k_place <<<(e + T - 1) / T, T>>>(src, dst, e);
    k_xform <<<(n + XB - 1) / XB, XB>>>(x, W1, n);
    k_gather1<<<(n * 32 + T - 1) / T, T>>>(b1, n);
    k_gather2<<<(n * 32 + T - 1) / T, T>>>(W2, b2, out, n);
}